// round 16
// baseline (speedup 1.0000x reference)
#include <cuda_runtime.h>
#include <cuda_fp16.h>

#define NB 2048
#define NF 4096
#define NC 8192
#define NT 8
#define NK 1024
#define NS 8
#define MB 8            // batch rows per tile (fp16, 8 rows per 16B slot)
#define THREADS 512     // 2 k per thread; target 3 CTAs/SM (64 KB smem each)
#define KPT 2

// 16-bit slot table, layout [s][k][t]: index = (s*NK + k)*NT + t.
// slot = feat | (sign>0 ? 0 : 0x1000); smem byte addr = (slot&0xFFF)*16.
// smem holds ONLY x ([feat][8 rows] fp16 = 64 KB); negative literal is
// synthesized: lit = fma(m, x, c), m=±1, c={0,1}.
// Slots within each (k,s) group are shaped (sorted by bank group, rotated
// by k&7) to reduce LDS conflict phases.
__device__ unsigned short g_slot[NS * NK * NT];   // 128 KB

__global__ void prep_kernel(const int* __restrict__ conj_feat,
                            const int* __restrict__ conj_sign,
                            const int* __restrict__ class_conj) {
    int i = blockIdx.x * blockDim.x + threadIdx.x;   // i = s*NK + k (k fast)
    if (i >= NS * NK) return;
    int s = i >> 10;
    int k = i & (NK - 1);
    int c = class_conj[k * NS + s];

    const int4* fp = (const int4*)(conj_feat + (size_t)c * NT);
    const int4* sp = (const int4*)(conj_sign + (size_t)c * NT);
    int4 f0 = fp[0], f1 = fp[1];
    int4 s0 = sp[0], s1 = sp[1];

    unsigned a[8];
    a[0] = (unsigned)f0.x | (s0.x > 0 ? 0u : 0x1000u);
    a[1] = (unsigned)f0.y | (s0.y > 0 ? 0u : 0x1000u);
    a[2] = (unsigned)f0.z | (s0.z > 0 ? 0u : 0x1000u);
    a[3] = (unsigned)f0.w | (s0.w > 0 ? 0u : 0x1000u);
    a[4] = (unsigned)f1.x | (s1.x > 0 ? 0u : 0x1000u);
    a[5] = (unsigned)f1.y | (s1.y > 0 ? 0u : 0x1000u);
    a[6] = (unsigned)f1.z | (s1.z > 0 ? 0u : 0x1000u);
    a[7] = (unsigned)f1.w | (s1.w > 0 ? 0u : 0x1000u);

    // Batcher odd-even sort by bank group (feat & 7); static indices only.
#define CSWP(p, q) do { \
        if ((a[p] & 7u) > (a[q] & 7u)) { unsigned _t = a[p]; a[p] = a[q]; a[q] = _t; } \
    } while (0)
    CSWP(0,1); CSWP(2,3); CSWP(4,5); CSWP(6,7);
    CSWP(0,2); CSWP(1,3); CSWP(4,6); CSWP(5,7);
    CSWP(1,2); CSWP(5,6);
    CSWP(0,4); CSWP(1,5); CSWP(2,6); CSWP(3,7);
    CSWP(2,4); CSWP(3,5);
    CSWP(1,2); CSWP(3,4); CSWP(5,6);
#undef CSWP

    int r = k & 7;                       // rotate by k&7 (stratify per warp)
    #pragma unroll
    for (int st = 0; st < 3; st++) {
        int amt = 1 << st;
        if (r & amt) {
            unsigned tmp[8];
            #pragma unroll
            for (int j = 0; j < 8; j++) tmp[j] = a[(j + amt) & 7];
            #pragma unroll
            for (int j = 0; j < 8; j++) a[j] = tmp[j];
        }
    }

    uint4 w;
    w.x = a[0] | (a[1] << 16);
    w.y = a[2] | (a[3] << 16);
    w.z = a[4] | (a[5] << 16);
    w.w = a[6] | (a[7] << 16);
    ((uint4*)g_slot)[i] = w;
}

static __device__ __forceinline__ unsigned hfma2u(unsigned a, unsigned b, unsigned c) {
    __half2 ha = *reinterpret_cast<__half2*>(&a);
    __half2 hb = *reinterpret_cast<__half2*>(&b);
    __half2 hc = *reinterpret_cast<__half2*>(&c);
    __half2 hr = __hfma2(ha, hb, hc);
    return *reinterpret_cast<unsigned*>(&hr);
}
static __device__ __forceinline__ unsigned hmul2u(unsigned a, unsigned b) {
    __half2 ha = *reinterpret_cast<__half2*>(&a);
    __half2 hb = *reinterpret_cast<__half2*>(&b);
    __half2 hr = __hmul2(ha, hb);
    return *reinterpret_cast<unsigned*>(&hr);
}
static __device__ __forceinline__ unsigned hmax2u(unsigned a, unsigned b) {
    __half2 ha = *reinterpret_cast<__half2*>(&a);
    __half2 hb = *reinterpret_cast<__half2*>(&b);
    __half2 hr = __hmax2(ha, hb);
    return *reinterpret_cast<unsigned*>(&hr);
}
static __device__ __forceinline__ uint4 mulh8(uint4 a, uint4 b) {
    a.x = hmul2u(a.x, b.x); a.y = hmul2u(a.y, b.y);
    a.z = hmul2u(a.z, b.z); a.w = hmul2u(a.w, b.w);
    return a;
}
static __device__ __forceinline__ uint4 maxh8(uint4 a, uint4 b) {
    a.x = hmax2u(a.x, b.x); a.y = hmax2u(a.y, b.y);
    a.z = hmax2u(a.z, b.z); a.w = hmax2u(a.w, b.w);
    return a;
}
static __device__ __forceinline__ unsigned pack2(float a, float b) {
    __half2 h = __floats2half2_rn(a, b);
    return *reinterpret_cast<unsigned*>(&h);
}

// Load one literal's 8 rows and apply the sign: lit = fma(±1, x, {0,1}).
static __device__ __forceinline__ uint4 literal(const char* sb, unsigned v) {
    uint4 q = *(const uint4*)(sb + ((v & 0xFFFu) << 4));
    bool neg = (v & 0x1000u) != 0;
    unsigned m2 = neg ? 0xBC00BC00u : 0x3C003C00u;   // -1 or +1 (half2)
    unsigned c2 = neg ? 0x3C003C00u : 0x00000000u;   //  1 or  0 (half2)
    q.x = hfma2u(q.x, m2, c2);
    q.y = hfma2u(q.y, m2, c2);
    q.z = hfma2u(q.z, m2, c2);
    q.w = hfma2u(q.w, m2, c2);
    return q;
}

// Same multiply tree as before: ((l0 l1)(l2 l3))((l4 l5)(l6 l7)) — but
// expressed in pair-sized chunks so the live register set stays small
// under the 42-reg cap (3 CTAs/SM).
static __device__ __forceinline__ uint4 sgroup(const char* sb, uint4 t) {
    uint4 p01 = mulh8(literal(sb, t.x & 0xFFFFu), literal(sb, t.x >> 16));
    uint4 p23 = mulh8(literal(sb, t.y & 0xFFFFu), literal(sb, t.y >> 16));
    uint4 pa  = mulh8(p01, p23);
    uint4 p45 = mulh8(literal(sb, t.z & 0xFFFFu), literal(sb, t.z >> 16));
    uint4 p67 = mulh8(literal(sb, t.w & 0xFFFFu), literal(sb, t.w >> 16));
    return mulh8(pa, mulh8(p45, p67));
}

static __device__ __forceinline__ void store_k(float* out, int b0, int k, uint4 mx) {
    float2 r01 = __half22float2(*reinterpret_cast<__half2*>(&mx.x));
    float2 r23 = __half22float2(*reinterpret_cast<__half2*>(&mx.y));
    float2 r45 = __half22float2(*reinterpret_cast<__half2*>(&mx.z));
    float2 r67 = __half22float2(*reinterpret_cast<__half2*>(&mx.w));
    out[(size_t)(b0 + 0) * NK + k] = r01.x;
    out[(size_t)(b0 + 1) * NK + k] = r01.y;
    out[(size_t)(b0 + 2) * NK + k] = r23.x;
    out[(size_t)(b0 + 3) * NK + k] = r23.y;
    out[(size_t)(b0 + 4) * NK + k] = r45.x;
    out[(size_t)(b0 + 5) * NK + k] = r45.y;
    out[(size_t)(b0 + 6) * NK + k] = r67.x;
    out[(size_t)(b0 + 7) * NK + k] = r67.y;
}

__global__ void __launch_bounds__(THREADS, 3)
dnf_kernel(const float* __restrict__ x, float* __restrict__ out) {
    extern __shared__ unsigned smem_u[];   // 64 KB: [4096 feat][4 u32] (x only)
    const int b0 = blockIdx.x * MB;

    // Phase A: stage x only. f = tid stride (coalesced LDG); STS.128
    // conflict-free (16B lane stride).
    uint4* slots = (uint4*)smem_u;
    for (int f = threadIdx.x; f < NF; f += THREADS) {
        float v[MB];
        #pragma unroll
        for (int r = 0; r < MB; r++)
            v[r] = x[(size_t)(b0 + r) * NF + f];
        uint4 hx;
        hx.x = pack2(v[0], v[1]);
        hx.y = pack2(v[2], v[3]);
        hx.z = pack2(v[4], v[5]);
        hx.w = pack2(v[6], v[7]);
        slots[f] = hx;
    }
    __syncthreads();

    const char* sb = (const char*)smem_u;

    #pragma unroll
    for (int kk = 0; kk < KPT; kk++) {
        const int k = threadIdx.x + kk * THREADS;
        const uint4* tab = (const uint4*)g_slot + k;   // tab[s*NK]

        uint4 ta = tab[0];
        uint4 mx = make_uint4(0u, 0u, 0u, 0u);         // products >= 0

        #pragma unroll
        for (int s = 0; s < NS; s++) {
            uint4 tn;
            if (s < NS - 1) tn = tab[(s + 1) * NK];    // 1-ahead prefetch
            mx = maxh8(mx, sgroup(sb, ta));
            if (s < NS - 1) ta = tn;
        }
        store_k(out, b0, k, mx);
    }
}

extern "C" void kernel_launch(void* const* d_in, const int* in_sizes, int n_in,
                              void* d_out, int out_size) {
    const float* x  = (const float*)d_in[0];
    const int*   cf = (const int*)d_in[1];
    const int*   cs = (const int*)d_in[2];
    const int*   cc = (const int*)d_in[3];
    float* out = (float*)d_out;

    prep_kernel<<<(NS * NK + 255) / 256, 256>>>(cf, cs, cc);

    size_t smem_bytes = (size_t)NF * MB * sizeof(__half);  // 65536
    cudaFuncSetAttribute(dnf_kernel,
                         cudaFuncAttributeMaxDynamicSharedMemorySize,
                         (int)smem_bytes);
    dnf_kernel<<<NB / MB, THREADS, smem_bytes>>>(x, out);
}